// round 3
// baseline (speedup 1.0000x reference)
#include <cuda_runtime.h>
#include <math.h>

#define Bb 2
#define Hh 64
#define Ww 64
#define LL 4096
#define Cc 96
#define Ee 192
#define Nn 16
#define CATC 768

static __device__ float g_x2d  [Bb*Cc*LL];
static __device__ float g_cat  [Bb*CATC*LL];
static __device__ float g_xconv[Bb*Cc*LL];
static __device__ float g_xp   [Bb*LL*Ee];
static __device__ float g_zp   [Bb*LL*Ee];
static __device__ float g_delta[Bb*Ee*LL];
static __device__ float g_Bm   [Bb*LL*Nn];
static __device__ float g_Cm   [Bb*LL*Nn];
static __device__ int   g_ord  [4*LL];
static __device__ float g_yd   [4*Bb*LL*Ee];
static __device__ float g_clC  [Bb*Cc*LL];
static __device__ float g_cl   [Bb*LL*Ee];
static __device__ float g_WtIn [Cc*2*Ee];
static __device__ float g_WtCl [Cc*Ee];
static __device__ float g_WtOut[Ee*Cc];

__device__ __forceinline__ float siluf(float v){ return v / (1.f + __expf(-v)); }

// ---------------- scan orders ----------------
__global__ void k_orders(){
  int l = blockIdx.x*blockDim.x + threadIdx.x;
  if (l < LL){
    int r = l >> 6, k = l & 63;
    int i = Hh-1-r;
    int j = (r & 1) ? (Ww-1-k) : k;
    g_ord[0*LL + l] = i*Ww + j;
    int c = l >> 6, tt = l & 63;
    int i2 = (c & 1) ? (Hh-1-tt) : tt;
    g_ord[1*LL + l] = i2*Ww + c;
  }
  if (l < Hh+Ww-1){
    int d = l;
    int off = (d < 64) ? d*(d+1)/2 : 2080 + (d-64)*(191-d)/2;
    int i0 = (d > 63) ? d-63 : 0;
    int i1 = (d < 63) ? d : 63;
    for (int ii=i0; ii<=i1; ++ii){
      int pos = off + (ii - i0);
      int j = d - ii;
      g_ord[2*LL + pos] = ii*Ww + j;
      g_ord[3*LL + pos] = ii*Ww + (Ww-1-j);
    }
  }
}

// ---------------- weight transposes ----------------
__global__ void k_prepw(const float* __restrict__ inw, const float* __restrict__ clw,
                        const float* __restrict__ opw){
  int idx = blockIdx.x*blockDim.x + threadIdx.x;
  if (idx < 384*96){
    int j = idx/96, c = idx%96;
    g_WtIn[c*384 + j] = inw[idx];
  } else if (idx < 384*96 + 192*96){
    int r = idx - 384*96;
    int e = r/96, c = r%96;
    g_WtCl[c*192 + e] = clw[r];
  } else if (idx < 384*96 + 192*96 + 96*192){
    int r = idx - 384*96 - 192*96;
    int o = r/192, e = r%192;
    g_WtOut[e*96 + o] = opw[r];
  }
}

// ---------------- x [B,L,C] -> [B,C,L] ----------------
__global__ void k_transpose(const float* __restrict__ x){
  __shared__ float tile[32][33];
  int p0 = blockIdx.x*32, c0 = blockIdx.y*32, b = blockIdx.z;
  int tx = threadIdx.x, ty = threadIdx.y;
  #pragma unroll
  for (int r=0;r<32;r+=8)
    tile[ty+r][tx] = x[((size_t)(b*LL + p0+ty+r))*Cc + c0+tx];
  __syncthreads();
  #pragma unroll
  for (int r=0;r<32;r+=8)
    g_x2d[((size_t)(b*Cc + c0+ty+r))*LL + p0+tx] = tile[tx][ty+r];
}

// ---------------- 4 depthwise convs + silu ----------------
__global__ void k_conv(const float* __restrict__ wh, const float* __restrict__ wv,
                       const float* __restrict__ wd1, const float* __restrict__ wd2){
  int p = blockIdx.x*blockDim.x + threadIdx.x;
  int oc = blockIdx.y, b = blockIdx.z;
  int t = oc / Ee;
  int o = oc - t*Ee;
  int ic = o >> 1;
  const float* xin = g_x2d + (size_t)(b*Cc + ic)*LL;
  int i = p >> 6, j = p & 63;
  float acc = 0.f;
  if (t == 0){
    const float* w = wh + o*7;
    #pragma unroll
    for (int k=0;k<7;k++){ int jj=j-3+k; if (jj>=0 && jj<Ww) acc += w[k]*xin[i*Ww+jj]; }
  } else if (t == 1){
    const float* w = wv + o*7;
    #pragma unroll
    for (int k=0;k<7;k++){ int ii=i-3+k; if (ii>=0 && ii<Hh) acc += w[k]*xin[ii*Ww+j]; }
  } else {
    const float* w = ((t==2) ? wd1 : wd2) + o*49;
    #pragma unroll
    for (int ki=0;ki<7;ki++){
      int ii=i-3+ki;
      if (ii<0 || ii>=Hh) continue;
      #pragma unroll
      for (int kj=0;kj<7;kj++){
        int jj=j-3+kj;
        if (jj>=0 && jj<Ww) acc += w[ki*7+kj]*xin[ii*Ww+jj];
      }
    }
  }
  g_cat[(size_t)(b*CATC + oc)*LL + p] = siluf(acc);
}

// ---------------- fuse 1x1 ----------------
__global__ void k_fuse(const float* __restrict__ fw){
  __shared__ float sin_[32][64];
  __shared__ float sw_[96][32];
  int p0 = blockIdx.x*64; int b = blockIdx.y;
  int t = threadIdx.x;
  int tx = t & 63, ty = t >> 6;
  float acc[24];
  #pragma unroll
  for (int k=0;k<24;k++) acc[k]=0.f;
  for (int c0=0;c0<CATC;c0+=32){
    __syncthreads();
    for (int idx=t; idx<32*64; idx+=256){
      int cc=idx>>6, pp=idx&63;
      sin_[cc][pp] = g_cat[(size_t)(b*CATC + c0+cc)*LL + p0+pp];
    }
    for (int idx=t; idx<96*32; idx+=256){
      int o=idx>>5, cc=idx&31;
      sw_[o][cc] = fw[o*CATC + c0+cc];
    }
    __syncthreads();
    for (int cc=0;cc<32;++cc){
      float xv = sin_[cc][tx];
      #pragma unroll
      for (int k=0;k<24;++k) acc[k] += sw_[ty+4*k][cc]*xv;
    }
  }
  #pragma unroll
  for (int k=0;k<24;++k)
    g_xconv[(size_t)(b*Cc + ty+4*k)*LL + p0+tx] = acc[k];
}

// ---------------- in_proj ----------------
__global__ void k_inproj(){
  __shared__ float sx[96][16];
  int l0 = blockIdx.x*16; int b = blockIdx.y;
  int t = threadIdx.x;  // 384
  for (int idx=t; idx<96*16; idx+=384){
    int c=idx>>4, pp=idx&15;
    sx[c][pp] = g_xconv[(size_t)(b*Cc+c)*LL + l0+pp];
  }
  __syncthreads();
  float acc[16];
  #pragma unroll
  for (int p=0;p<16;p++) acc[p]=0.f;
  for (int c=0;c<96;++c){
    float wv = g_WtIn[c*384 + t];
    #pragma unroll
    for (int p=0;p<16;++p) acc[p] += wv*sx[c][p];
  }
  float* dst = (t < 192) ? g_xp : g_zp;
  int j = (t < 192) ? t : t-192;
  #pragma unroll
  for (int p=0;p<16;++p)
    dst[((size_t)b*LL + l0+p)*Ee + j] = acc[p];
}

// ---------------- x_proj + dt ----------------
__global__ void k_xproj(const float* __restrict__ xpw, const float* __restrict__ dtw,
                        const float* __restrict__ dtb){
  int b = blockIdx.y; int l0 = blockIdx.x*8;
  int t = threadIdx.x;   // 192
  __shared__ float swT[192*39];
  __shared__ float dtws[Ee*6];
  __shared__ float xs[Ee];
  __shared__ float xd[38];
  for (int idx=t; idx<38*192; idx+=192){
    int k = idx/192, c = idx%192;
    swT[c*39 + k] = xpw[idx];
  }
  for (int idx=t; idx<Ee*6; idx+=192) dtws[idx] = dtw[idx];
  float b2 = dtb[t];
  __syncthreads();
  for (int li=0; li<8; ++li){
    int l = l0 + li;
    xs[t] = g_xp[((size_t)b*LL + l)*Ee + t];
    __syncthreads();
    if (t < 38){
      float s = 0.f;
      for (int c=0;c<192;c++) s += swT[c*39 + t]*xs[c];
      xd[t] = s;
    }
    __syncthreads();
    float s = 0.f;
    #pragma unroll
    for (int r=0;r<6;r++) s += dtws[t*6+r]*xd[r];
    float xx = s + 2.f*b2;   // bias applied in dt AND as delta_bias (faithful)
    float delta = (xx > 20.f) ? xx : log1pf(__expf(xx));
    g_delta[((size_t)b*Ee + t)*LL + l] = delta;
    if (t < 16)       g_Bm[((size_t)(b*LL+l))*Nn + t]      = xd[6+t];
    else if (t < 32)  g_Cm[((size_t)(b*LL+l))*Nn + (t-16)] = xd[22+(t-16)];
    __syncthreads();
  }
}

// ---------------- 4-direction selective scan ----------------
__global__ void k_scan(const float* __restrict__ A_log, const float* __restrict__ dirB,
                       const float* __restrict__ Dv){
  int e = blockIdx.x, b = blockIdx.y;
  int t = threadIdx.x, w = t>>5, lane = t&31;
  int n = lane & 15, half = lane >> 4;
  int dX = half*2, dY = dX+1;
  __shared__ float smP[8][16];
  __shared__ float smS[8][64];
  float Ane = -__expf(A_log[e*Nn + n]);
  float dbx = dirB[dX*Nn + n];
  float dby = dirB[dY*Nn + n];
  float Dval = Dv[e];
  const float* dptr = g_delta + ((size_t)b*Ee + e)*LL;
  const int bL = b*LL;
  const int* ordX = g_ord + dX*LL;
  const int* ordY = g_ord + dY*LL;
  int l0 = w*512;

  float P = 1.f, sx = 0.f, sy = 0.f;
  for (int l=l0; l<l0+512; ++l){
    float delta = dptr[l];
    float Bv = g_Bm[(size_t)(bL+l)*Nn + n];
    int ox = ordX[l], oy = ordY[l];
    float ux = g_xp[((size_t)bL + ox)*Ee + e];
    float uy = g_xp[((size_t)bL + oy)*Ee + e];
    float dA = __expf(delta*Ane);
    float dB = delta*Bv;
    sx = dA*sx + (dB + delta*dbx)*ux;
    sy = dA*sy + (dB + delta*dby)*uy;
    P *= dA;
  }
  if (half == 0) smP[w][n] = P;
  smS[w][dX*16+n] = sx;
  smS[w][dY*16+n] = sy;
  __syncthreads();
  float hx = 0.f, hy = 0.f;
  for (int j=0;j<w;++j){
    float Pj = smP[j][n];
    hx = Pj*hx + smS[j][dX*16+n];
    hy = Pj*hy + smS[j][dY*16+n];
  }

  for (int l=l0; l<l0+512; ++l){
    float delta = dptr[l];
    float Bv = g_Bm[(size_t)(bL+l)*Nn + n];
    float Cv = g_Cm[(size_t)(bL+l)*Nn + n];
    int ox = ordX[l], oy = ordY[l];
    float ux = g_xp[((size_t)bL + ox)*Ee + e];
    float uy = g_xp[((size_t)bL + oy)*Ee + e];
    float dA = __expf(delta*Ane);
    float dB = delta*Bv;
    hx = dA*hx + (dB + delta*dbx)*ux;
    hy = dA*hy + (dB + delta*dby)*uy;
    float px = hx*Cv, py = hy*Cv;
    #pragma unroll
    for (int m=8;m;m>>=1){
      px += __shfl_xor_sync(0xffffffffu, px, m);
      py += __shfl_xor_sync(0xffffffffu, py, m);
    }
    if (n == 0){
      g_yd[((size_t)(dX*Bb + b)*LL + ox)*Ee + e] = px + Dval*ux;
      g_yd[((size_t)(dY*Bb + b)*LL + oy)*Ee + e] = py + Dval*uy;
    }
  }
}

// ---------------- local clustering ----------------
__global__ void k_cluster(const float* __restrict__ fw, const float* __restrict__ fb,
                          const float* __restrict__ vw, const float* __restrict__ vb,
                          const float* __restrict__ pw, const float* __restrict__ pb,
                          const float* __restrict__ salpha, const float* __restrict__ sbeta){
  __shared__ float xw[96][64];
  __shared__ float fsh[6][64], vsh[6][64];
  __shared__ float cen[6][25], vc[6][25];
  __shared__ float cnorm[25], fnorm[64];
  __shared__ float ssim[25][64];
  __shared__ int   kidx[64];
  __shared__ float sval[64];
  __shared__ float rowsum[25];
  __shared__ float agg[25][6];
  __shared__ float outw[6][64];

  int wi = blockIdx.x;
  int b = wi >> 6, Wg = (wi >> 3) & 7, Hg = wi & 7;
  int t = threadIdx.x;   // 128

  for (int idx=t; idx<96*64; idx+=128){
    int c=idx>>6, pp=idx&63;
    int i = Wg*8 + (pp>>3), j = Hg*8 + (pp&7);
    xw[c][pp] = g_xconv[(size_t)(b*Cc+c)*LL + i*Ww + j];
  }
  __syncthreads();
  for (int idx=t; idx<2*6*64; idx+=128){
    int which = idx/384; int r = idx%384;
    int o = r>>6, pp = r&63;
    if (!which){
      float a = fb[o];
      for (int c=0;c<48;c++) a += fw[o*48+c]*xw[c][pp];
      fsh[o][pp] = a;
    } else {
      float a = vb[o];
      for (int c=0;c<48;c++) a += vw[o*48+c]*xw[48+c][pp];
      vsh[o][pp] = a;
    }
  }
  __syncthreads();
  for (int idx=t; idx<2*6*25; idx+=128){
    int which = idx/150; int r = idx%150;
    int o = r/25, k = r%25;
    int ii = k/5, jj = k%5;
    int si=(ii*8)/5, ei=((ii+1)*8+4)/5, sj=(jj*8)/5, ej=((jj+1)*8+4)/5;
    float s = 0.f;
    for (int iw=si; iw<ei; iw++)
      for (int ih=sj; ih<ej; ih++)
        s += (which ? vsh[o][iw*8+ih] : fsh[o][iw*8+ih]);
    s /= (float)((ei-si)*(ej-sj));
    if (which) vc[o][k]=s; else cen[o][k]=s;
  }
  __syncthreads();
  if (t < 25){
    float s=0.f;
    for (int o=0;o<6;o++){ float v=cen[o][t]; s+=v*v; }
    cnorm[t] = fmaxf(sqrtf(s), 1e-12f);
  } else if (t >= 64 && t < 128){
    int pp = t-64;
    float s=0.f;
    for (int o=0;o<6;o++){ float v=fsh[o][pp]; s+=v*v; }
    fnorm[pp] = fmaxf(sqrtf(s), 1e-12f);
  }
  __syncthreads();
  float alpha = salpha[0], beta = sbeta[0];
  for (int idx=t; idx<25*64; idx+=128){
    int k = idx/64, pp = idx%64;
    float dp = 0.f;
    for (int o=0;o<6;o++) dp += cen[o][k]*fsh[o][pp];
    float xarg = beta + alpha*dp/(cnorm[k]*fnorm[pp]);
    ssim[k][pp] = 1.f/(1.f + expf(-xarg));
  }
  __syncthreads();
  if (t < 64){
    float best = -1e30f; int bk = 0;
    for (int k=0;k<25;k++){ float s = ssim[k][t]; if (s > best){ best = s; bk = k; } }
    kidx[t] = bk; sval[t] = best;
  }
  __syncthreads();
  if (t < 25){
    float rs = 0.f;
    for (int p=0;p<64;p++) if (kidx[p]==t) rs += sval[p];
    rowsum[t] = rs;
  }
  __syncthreads();
  for (int idx=t; idx<25*6; idx+=128){
    int k = idx/6, c = idx%6;
    float s = 0.f;
    for (int p=0;p<64;p++) if (kidx[p]==k) s += sval[p]*vsh[c][p];
    agg[k][c] = (s + vc[c][k]) / (rowsum[k] + 1.f);
  }
  __syncthreads();
  for (int idx=t; idx<6*64; idx+=128){
    int c = idx/64, p = idx%64;
    outw[c][p] = agg[kidx[p]][c]*sval[p];
  }
  __syncthreads();
  for (int idx=t; idx<96*64; idx+=128){
    int o = idx>>6, p = idx&63;
    float a = pb[o];
    #pragma unroll
    for (int c=0;c<6;c++) a += pw[o*6+c]*outw[c][p];
    int i = Wg*8+(p>>3), j = Hg*8+(p&7);
    g_clC[(size_t)(b*Cc+o)*LL + i*Ww+j] = a;
  }
}

// ---------------- cluster_proj ----------------
__global__ void k_clproj(const float* __restrict__ cpb){
  __shared__ float sx[96][16];
  int l0 = blockIdx.x*16; int b = blockIdx.y;
  int t = threadIdx.x;  // 192
  for (int idx=t; idx<96*16; idx+=192){
    int c=idx>>4, pp=idx&15;
    sx[c][pp] = g_clC[(size_t)(b*Cc+c)*LL + l0+pp];
  }
  __syncthreads();
  float acc[16]; float bi = cpb[t];
  #pragma unroll
  for (int p=0;p<16;p++) acc[p]=bi;
  for (int c=0;c<96;++c){
    float wv = g_WtCl[c*192+t];
    #pragma unroll
    for (int p=0;p<16;++p) acc[p] += wv*sx[c][p];
  }
  #pragma unroll
  for (int p=0;p<16;++p)
    g_cl[((size_t)b*LL + l0+p)*Ee + t] = acc[p];
}

// ---------------- LN mix + out_proj ----------------
__global__ void k_mix(const float* __restrict__ lnw, const float* __restrict__ lnb,
                      const float* __restrict__ bch, float* __restrict__ out){
  int b = blockIdx.y; int l0 = blockIdx.x*8;
  int t = threadIdx.x;  // 192
  int w = t>>5, lane = t&31;
  __shared__ float sy[192][9];
  __shared__ float red[6][6];
  float lw = lnw[t], lb = lnb[t];
  float b0 = bch[t], b1 = bch[192+t], b2 = bch[384+t];
  float mx = fmaxf(b0, fmaxf(b1,b2));
  float e0=__expf(b0-mx), e1=__expf(b1-mx), e2=__expf(b2-mx);
  float inv = 1.f/(e0+e1+e2);
  float w0=e0*inv, w1=e1*inv, w2=e2*inv;
  const size_t DS = (size_t)Bb*LL*Ee;
  for (int li=0; li<8; ++li){
    int l = l0+li;
    size_t base = ((size_t)b*LL + l)*Ee + t;
    float ysv = g_yd[base] + g_yd[base+DS] + g_yd[base+2*DS] + g_yd[base+3*DS];
    float zv = g_zp[base];
    float cv = g_cl[base];
    float s1=ysv, q1=ysv*ysv, s2=zv, q2=zv*zv, s3=cv, q3=cv*cv;
    #pragma unroll
    for (int m=16;m;m>>=1){
      s1 += __shfl_xor_sync(0xffffffffu, s1, m);
      q1 += __shfl_xor_sync(0xffffffffu, q1, m);
      s2 += __shfl_xor_sync(0xffffffffu, s2, m);
      q2 += __shfl_xor_sync(0xffffffffu, q2, m);
      s3 += __shfl_xor_sync(0xffffffffu, s3, m);
      q3 += __shfl_xor_sync(0xffffffffu, q3, m);
    }
    if (lane==0){ red[w][0]=s1; red[w][1]=q1; red[w][2]=s2; red[w][3]=q2; red[w][4]=s3; red[w][5]=q3; }
    __syncthreads();
    float S1=0,Q1=0,S2=0,Q2=0,S3=0,Q3=0;
    #pragma unroll
    for (int j=0;j<6;j++){ S1+=red[j][0]; Q1+=red[j][1]; S2+=red[j][2]; Q2+=red[j][3]; S3+=red[j][4]; Q3+=red[j][5]; }
    const float iE = 1.f/192.f;
    float m1=S1*iE, v1=Q1*iE-m1*m1;
    float m2=S2*iE, v2=Q2*iE-m2*m2;
    float m3=S3*iE, v3=Q3*iE-m3*m3;
    float r1=rsqrtf(v1+1e-5f), r2=rsqrtf(v2+1e-5f), r3=rsqrtf(v3+1e-5f);
    float ln1=(ysv-m1)*r1*lw+lb;
    float ln2=(zv -m2)*r2*lw+lb;
    float ln3=(cv -m3)*r3*lw+lb;
    sy[t][li] = w0*ln1 + w1*ln2 + w2*ln3;
    __syncthreads();
  }
  int o = t%96, hf = t/96;
  float acc[4] = {0.f,0.f,0.f,0.f};
  for (int e=0;e<192;e++){
    float wv = g_WtOut[e*96+o];
    #pragma unroll
    for (int p=0;p<4;p++) acc[p] += wv*sy[e][hf*4+p];
  }
  #pragma unroll
  for (int p=0;p<4;p++)
    out[((size_t)b*LL + l0+hf*4+p)*Cc + o] = acc[p];
}

extern "C" void kernel_launch(void* const* d_in, const int* in_sizes, int n_in,
                              void* d_out, int out_size){
  const float* x    = (const float*)d_in[0];
  const float* wh   = (const float*)d_in[3];
  const float* wv   = (const float*)d_in[4];
  const float* wd1  = (const float*)d_in[5];
  const float* wd2  = (const float*)d_in[6];
  const float* fw   = (const float*)d_in[7];
  const float* inw  = (const float*)d_in[8];
  const float* xpw  = (const float*)d_in[9];
  const float* dtw  = (const float*)d_in[10];
  const float* dtb  = (const float*)d_in[11];
  const float* alog = (const float*)d_in[12];
  const float* Dv   = (const float*)d_in[13];
  const float* dirB = (const float*)d_in[14];
  const float* opw  = (const float*)d_in[15];
  const float* sal  = (const float*)d_in[16];
  const float* sbe  = (const float*)d_in[17];
  const float* f_w  = (const float*)d_in[18];
  const float* f_b  = (const float*)d_in[19];
  const float* v_w  = (const float*)d_in[20];
  const float* v_b  = (const float*)d_in[21];
  const float* p_w  = (const float*)d_in[22];
  const float* p_b  = (const float*)d_in[23];
  const float* cpb  = (const float*)d_in[25];
  const float* bch  = (const float*)d_in[26];
  const float* lnw  = (const float*)d_in[27];
  const float* lnb  = (const float*)d_in[28];
  float* out = (float*)d_out;

  k_orders<<<32, 128>>>();
  k_prepw<<<288, 256>>>(inw, (const float*)d_in[24], opw);
  k_transpose<<<dim3(LL/32, Cc/32, Bb), dim3(32,8)>>>(x);
  k_conv<<<dim3(LL/128, CATC, Bb), 128>>>(wh, wv, wd1, wd2);
  k_fuse<<<dim3(LL/64, Bb), 256>>>(fw);
  k_inproj<<<dim3(LL/16, Bb), 384>>>();
  k_xproj<<<dim3(LL/8, Bb), 192>>>(xpw, dtw, dtb);
  k_scan<<<dim3(Ee, Bb), 256>>>(alog, dirB, Dv);
  k_cluster<<<Bb*64, 128>>>(f_w, f_b, v_w, v_b, p_w, p_b, sal, sbe);
  k_clproj<<<dim3(LL/16, Bb), 192>>>(cpb);
  k_mix<<<dim3(LL/8, Bb), 192>>>(lnw, lnb, bch, out);
}